// round 8
// baseline (speedup 1.0000x reference)
#include <cuda_runtime.h>

#define MAXABS_BLOCKS 2048

// Scratch (written unconditionally each run -> no init kernel needed).
__device__ unsigned int g_partial[MAXABS_BLOCKS];
__device__ unsigned int g_max_bits;
__device__ unsigned int g_ticket;   // zero-init; reset each run by last block

// ---------------------------------------------------------------------------
// Pass 1: per-block max|x|, REVERSE traversal (front of x stays in L2 for the
// quant kernel's forward read). Last block folds the final reduction.
// ---------------------------------------------------------------------------
__global__ __launch_bounds__(256) void hx_maxabs_kernel(
    const float4* __restrict__ x, int n4) {
    float m = 0.0f;
    const int stride = gridDim.x * blockDim.x;
    int i = blockIdx.x * blockDim.x + threadIdx.x;
    for (; i + 3 * stride < n4; i += 4 * stride) {
        float4 a = x[n4 - 1 - i];
        float4 b = x[n4 - 1 - (i + stride)];
        float4 c = x[n4 - 1 - (i + 2 * stride)];
        float4 d = x[n4 - 1 - (i + 3 * stride)];
        float ma = fmaxf(fmaxf(fabsf(a.x), fabsf(a.y)), fmaxf(fabsf(a.z), fabsf(a.w)));
        float mb = fmaxf(fmaxf(fabsf(b.x), fabsf(b.y)), fmaxf(fabsf(b.z), fabsf(b.w)));
        float mc = fmaxf(fmaxf(fabsf(c.x), fabsf(c.y)), fmaxf(fabsf(c.z), fabsf(c.w)));
        float md = fmaxf(fmaxf(fabsf(d.x), fabsf(d.y)), fmaxf(fabsf(d.z), fabsf(d.w)));
        m = fmaxf(m, fmaxf(fmaxf(ma, mb), fmaxf(mc, md)));
    }
    for (; i < n4; i += stride) {
        float4 v = x[n4 - 1 - i];
        m = fmaxf(m, fmaxf(fmaxf(fabsf(v.x), fabsf(v.y)),
                           fmaxf(fabsf(v.z), fabsf(v.w))));
    }
#pragma unroll
    for (int o = 16; o > 0; o >>= 1)
        m = fmaxf(m, __shfl_xor_sync(0xffffffffu, m, o));
    __shared__ float warpmax[8];
    __shared__ bool is_last;
    const int lane = threadIdx.x & 31, wid = threadIdx.x >> 5;
    if (lane == 0) warpmax[wid] = m;
    __syncthreads();
    if (threadIdx.x == 0) {
        float bm = warpmax[0];
#pragma unroll
        for (int w = 1; w < 8; ++w) bm = fmaxf(bm, warpmax[w]);
        g_partial[blockIdx.x] = __float_as_uint(bm);
        __threadfence();
        unsigned int t = atomicAdd(&g_ticket, 1u);
        is_last = (t == (unsigned int)(gridDim.x - 1));
    }
    __syncthreads();

    if (is_last) {
        float r = 0.0f;
#pragma unroll
        for (int k = 0; k < MAXABS_BLOCKS / 256; ++k)
            r = fmaxf(r, __uint_as_float(g_partial[threadIdx.x + 256 * k]));
#pragma unroll
        for (int o = 16; o > 0; o >>= 1)
            r = fmaxf(r, __shfl_xor_sync(0xffffffffu, r, o));
        if (lane == 0) warpmax[wid] = r;
        __syncthreads();
        if (threadIdx.x == 0) {
            float bm = warpmax[0];
#pragma unroll
            for (int w = 1; w < 8; ++w) bm = fmaxf(bm, warpmax[w]);
            g_max_bits = __float_as_uint(bm);
            g_ticket = 0u;   // graph-replay determinism
        }
    }
}

// Lean tanh for the scalar M: exp2 (MUFU.EX2) + rcp divide, ~2 ulp.
__device__ __forceinline__ float hx_tanh(float x) {
    float cx = fminf(x, 30.0f);
    float e  = exp2f(cx * 2.8853900817779268f);     // exp(2*x)
    return __fdividef(e - 1.0f, e + 1.0f);
}

// Descending comparator on floats (2x FMNMX).
#define HX_CSWAP(a, b) { float _hi = fmaxf(a, b); b = fminf(a, b); a = _hi; }

// ---------------------------------------------------------------------------
// Pass 2: quantize + per-group (8 channels, stride 9) top-4 keep.
// Each block stages 4608 contiguous floats (64 segments of 72 = 8ch x 9hw)
// in SMEM via 4 front-batched float4 loads per thread (MLP_p1=4); each of
// 288 threads owns TWO groups of 8 stride-9 cells, processed sequentially.
// s*tanh via s - 2s/(e+1) (one fewer op on the MUFU-serial chain).
// ---------------------------------------------------------------------------
__global__ __launch_bounds__(288, 6) void hx_quant_kernel(
    const float* __restrict__ x, float* __restrict__ out,
    const int* __restrict__ bits_ptr) {
    __shared__ __align__(16) float tile[4608];
    const int tid = threadIdx.x;
    const long long blk = (long long)blockIdx.x * 4608;
    const float4* in4 = (const float4*)(x + blk);
    float4* out4 = (float4*)(out + blk);
    float4* t4 = (float4*)tile;

    // 4 front-batched 16B loads per thread (1152 float4 per block).
    t4[tid]       = in4[tid];
    t4[tid + 288] = in4[tid + 288];
    t4[tid + 576] = in4[tid + 576];
    t4[tid + 864] = in4[tid + 864];
    __syncthreads();

    const float delta     = (float)((1 << (bits_ptr[0] - 1)) - 1);  // 127
    const float M         = hx_tanh(fabsf(__uint_as_float(g_max_bits)));
    const float s         = __fdiv_rn(delta, M);
    const float n2s       = -2.0f * s;
    const float inv_delta = __fdiv_rn(1.0f, delta);
    const float K2        = 2.8853900817779268f;    // 2*log2(e)

    const int seg  = tid / 9;          // 0..31
    const int hw   = tid - seg * 9;    // 0..8

#pragma unroll
    for (int g = 0; g < 2; ++g) {
        const int base = (seg + 32 * g) * 72 + hw;

        float vf[8];     // rounded quantized value (integer-valued float)
        float key[8];    // |vf|*8 + (7-k): exact in fp32, all distinct
#pragma unroll
        for (int k = 0; k < 8; ++k) {
            float xx = tile[base + 9 * k];
            float e  = exp2f(fminf(xx, 30.0f) * K2);    // exp(2x)
            // s*tanh(x) = s - 2s/(e+1)
            float v  = rintf(fmaf(n2s, __frcp_rn(e + 1.0f), s));
            vf[k]  = v;
            key[k] = fmaf(fabsf(v), 8.0f, (float)(7 - k));
        }

        // thr = 4th-largest key of 8: sort halves of 4 desc, merge-select.
        float a0 = key[0], a1 = key[1], a2 = key[2], a3 = key[3];
        float b0 = key[4], b1 = key[5], b2 = key[6], b3 = key[7];
        HX_CSWAP(a0, a1); HX_CSWAP(a2, a3); HX_CSWAP(a0, a2); HX_CSWAP(a1, a3); HX_CSWAP(a1, a2);
        HX_CSWAP(b0, b1); HX_CSWAP(b2, b3); HX_CSWAP(b0, b2); HX_CSWAP(b1, b3); HX_CSWAP(b1, b2);
        float thr = fmaxf(fmaxf(a3, b3),
                          fmaxf(fminf(a0, b2), fmaxf(fminf(a1, b1), fminf(a2, b0))));

#pragma unroll
        for (int i = 0; i < 8; ++i) {
            float sel = (key[i] >= thr) ? vf[i] : 0.0f;
            tile[base + 9 * i] = sel * inv_delta;
        }
    }
    __syncthreads();

    // Streaming stores: out is never re-read; keep x resident in L2.
    __stcs(&out4[tid],       t4[tid]);
    __stcs(&out4[tid + 288], t4[tid + 288]);
    __stcs(&out4[tid + 576], t4[tid + 576]);
    __stcs(&out4[tid + 864], t4[tid + 864]);
}

extern "C" void kernel_launch(void* const* d_in, const int* in_sizes, int n_in,
                              void* d_out, int out_size) {
    const float* x  = (const float*)d_in[0];
    const int* bits = (const int*)d_in[1];
    float* out      = (float*)d_out;

    const int n  = in_sizes[0];          // 37748736
    const int n4 = n >> 2;
    const int qblocks = n / 4608;        // 8192 (exact)

    hx_maxabs_kernel<<<MAXABS_BLOCKS, 256>>>((const float4*)x, n4);
    hx_quant_kernel<<<qblocks, 288>>>(x, out, bits);
}

// round 9
// speedup vs baseline: 1.0376x; 1.0376x over previous
#include <cuda_runtime.h>

#define MAXABS_BLOCKS 2048

// Scratch (written unconditionally each run -> no init kernel needed).
__device__ unsigned int g_partial[MAXABS_BLOCKS];
__device__ unsigned int g_max_bits;
__device__ unsigned int g_ticket;   // zero-init; reset each run by last block

// ---------------------------------------------------------------------------
// Pass 1: per-block max|x|, REVERSE traversal (front of x stays in L2 for the
// quant kernel's forward read). Last block folds the final reduction.
// ---------------------------------------------------------------------------
__global__ __launch_bounds__(256) void hx_maxabs_kernel(
    const float4* __restrict__ x, int n4) {
    float m = 0.0f;
    const int stride = gridDim.x * blockDim.x;
    int i = blockIdx.x * blockDim.x + threadIdx.x;
    for (; i + 3 * stride < n4; i += 4 * stride) {
        float4 a = x[n4 - 1 - i];
        float4 b = x[n4 - 1 - (i + stride)];
        float4 c = x[n4 - 1 - (i + 2 * stride)];
        float4 d = x[n4 - 1 - (i + 3 * stride)];
        float ma = fmaxf(fmaxf(fabsf(a.x), fabsf(a.y)), fmaxf(fabsf(a.z), fabsf(a.w)));
        float mb = fmaxf(fmaxf(fabsf(b.x), fabsf(b.y)), fmaxf(fabsf(b.z), fabsf(b.w)));
        float mc = fmaxf(fmaxf(fabsf(c.x), fabsf(c.y)), fmaxf(fabsf(c.z), fabsf(c.w)));
        float md = fmaxf(fmaxf(fabsf(d.x), fabsf(d.y)), fmaxf(fabsf(d.z), fabsf(d.w)));
        m = fmaxf(m, fmaxf(fmaxf(ma, mb), fmaxf(mc, md)));
    }
    for (; i < n4; i += stride) {
        float4 v = x[n4 - 1 - i];
        m = fmaxf(m, fmaxf(fmaxf(fabsf(v.x), fabsf(v.y)),
                           fmaxf(fabsf(v.z), fabsf(v.w))));
    }
#pragma unroll
    for (int o = 16; o > 0; o >>= 1)
        m = fmaxf(m, __shfl_xor_sync(0xffffffffu, m, o));
    __shared__ float warpmax[8];
    __shared__ bool is_last;
    const int lane = threadIdx.x & 31, wid = threadIdx.x >> 5;
    if (lane == 0) warpmax[wid] = m;
    __syncthreads();
    if (threadIdx.x == 0) {
        float bm = warpmax[0];
#pragma unroll
        for (int w = 1; w < 8; ++w) bm = fmaxf(bm, warpmax[w]);
        g_partial[blockIdx.x] = __float_as_uint(bm);
        __threadfence();
        unsigned int t = atomicAdd(&g_ticket, 1u);
        is_last = (t == (unsigned int)(gridDim.x - 1));
    }
    __syncthreads();

    if (is_last) {
        float r = 0.0f;
#pragma unroll
        for (int k = 0; k < MAXABS_BLOCKS / 256; ++k)
            r = fmaxf(r, __uint_as_float(g_partial[threadIdx.x + 256 * k]));
#pragma unroll
        for (int o = 16; o > 0; o >>= 1)
            r = fmaxf(r, __shfl_xor_sync(0xffffffffu, r, o));
        if (lane == 0) warpmax[wid] = r;
        __syncthreads();
        if (threadIdx.x == 0) {
            float bm = warpmax[0];
#pragma unroll
            for (int w = 1; w < 8; ++w) bm = fmaxf(bm, warpmax[w]);
            g_max_bits = __float_as_uint(bm);
            g_ticket = 0u;   // graph-replay determinism
        }
    }
}

// Single-MUFU approximate reciprocal (what __fdividef uses internally).
__device__ __forceinline__ float hx_rcp(float x) {
    float r;
    asm("rcp.approx.f32 %0, %1;" : "=f"(r) : "f"(x));
    return r;
}

// Lean tanh for the scalar M: exp2 (MUFU.EX2) + rcp divide, ~2 ulp.
__device__ __forceinline__ float hx_tanh(float x) {
    float cx = fminf(x, 30.0f);
    float e  = exp2f(cx * 2.8853900817779268f);     // exp(2*x)
    return __fdividef(e - 1.0f, e + 1.0f);
}

// Descending comparator on floats (2x FMNMX).
#define HX_CSWAP(a, b) { float _hi = fmaxf(a, b); b = fminf(a, b); a = _hi; }

// ---------------------------------------------------------------------------
// Pass 2: quantize + per-group (8 channels, stride 9) top-4 keep.
// Each block stages 4608 contiguous floats (64 segments of 72 = 8ch x 9hw)
// in SMEM via 4 front-batched float4 loads per thread (MLP_p1=4); each of
// 288 threads owns TWO groups of 8 stride-9 cells.
// Serial chain per element: EX2 -> FADD -> RCP(approx) -> FFMA -> FRND.
// ---------------------------------------------------------------------------
__global__ __launch_bounds__(288, 6) void hx_quant_kernel(
    const float* __restrict__ x, float* __restrict__ out,
    const int* __restrict__ bits_ptr) {
    __shared__ __align__(16) float tile[4608];
    const int tid = threadIdx.x;
    const long long blk = (long long)blockIdx.x * 4608;
    const float4* in4 = (const float4*)(x + blk);
    float4* out4 = (float4*)(out + blk);
    float4* t4 = (float4*)tile;

    // 4 front-batched 16B loads per thread (1152 float4 per block).
    t4[tid]       = in4[tid];
    t4[tid + 288] = in4[tid + 288];
    t4[tid + 576] = in4[tid + 576];
    t4[tid + 864] = in4[tid + 864];
    __syncthreads();

    const float delta     = (float)((1 << (bits_ptr[0] - 1)) - 1);  // 127
    const float M         = hx_tanh(fabsf(__uint_as_float(g_max_bits)));
    const float s         = __fdiv_rn(delta, M);
    const float n2s       = -2.0f * s;
    const float inv_delta = __fdiv_rn(1.0f, delta);
    const float K2        = 2.8853900817779268f;    // 2*log2(e)

    const int seg  = tid / 9;          // 0..31
    const int hw   = tid - seg * 9;    // 0..8

#pragma unroll
    for (int g = 0; g < 2; ++g) {
        const int base = (seg + 32 * g) * 72 + hw;

        float vf[8];     // rounded quantized value (integer-valued float)
        float key[8];    // |vf|*8 + (7-k): exact in fp32, all distinct
#pragma unroll
        for (int k = 0; k < 8; ++k) {
            float xx = tile[base + 9 * k];
            float e  = exp2f(fminf(xx, 30.0f) * K2);    // exp(2x)
            // s*tanh(x) = s - 2s/(e+1), approximate single-MUFU reciprocal
            float v  = rintf(fmaf(n2s, hx_rcp(e + 1.0f), s));
            vf[k]  = v;
            key[k] = fmaf(fabsf(v), 8.0f, (float)(7 - k));
        }

        // thr = 4th-largest key of 8: sort halves of 4 desc, merge-select.
        float a0 = key[0], a1 = key[1], a2 = key[2], a3 = key[3];
        float b0 = key[4], b1 = key[5], b2 = key[6], b3 = key[7];
        HX_CSWAP(a0, a1); HX_CSWAP(a2, a3); HX_CSWAP(a0, a2); HX_CSWAP(a1, a3); HX_CSWAP(a1, a2);
        HX_CSWAP(b0, b1); HX_CSWAP(b2, b3); HX_CSWAP(b0, b2); HX_CSWAP(b1, b3); HX_CSWAP(b1, b2);
        float thr = fmaxf(fmaxf(a3, b3),
                          fmaxf(fminf(a0, b2), fmaxf(fminf(a1, b1), fminf(a2, b0))));

#pragma unroll
        for (int i = 0; i < 8; ++i) {
            float sel = (key[i] >= thr) ? vf[i] : 0.0f;
            tile[base + 9 * i] = sel * inv_delta;
        }
    }
    __syncthreads();

    // Streaming stores: out is never re-read; keep x resident in L2.
    __stcs(&out4[tid],       t4[tid]);
    __stcs(&out4[tid + 288], t4[tid + 288]);
    __stcs(&out4[tid + 576], t4[tid + 576]);
    __stcs(&out4[tid + 864], t4[tid + 864]);
}

extern "C" void kernel_launch(void* const* d_in, const int* in_sizes, int n_in,
                              void* d_out, int out_size) {
    const float* x  = (const float*)d_in[0];
    const int* bits = (const int*)d_in[1];
    float* out      = (float*)d_out;

    const int n  = in_sizes[0];          // 37748736
    const int n4 = n >> 2;
    const int qblocks = n / 4608;        // 8192 (exact)

    hx_maxabs_kernel<<<MAXABS_BLOCKS, 256>>>((const float4*)x, n4);
    hx_quant_kernel<<<qblocks, 288>>>(x, out, bits);
}